// round 13
// baseline (speedup 1.0000x reference)
#include <cuda_runtime.h>
#include <cuda_bf16.h>
#include <math.h>
#include <stdint.h>

#define NB 128
#define TT 512
#define DD 1024
#define HH 1024

// ---------------- helpers (arch-agnostic PTX only: sm_80+ features) ----------
__device__ __forceinline__ uint32_t smem_u32(const void* p) {
    uint32_t a;
    asm("{ .reg .u64 t; cvta.to.shared.u64 t, %1; cvt.u32.u64 %0, t; }"
        : "=r"(a) : "l"(p));
    return a;
}
__device__ __forceinline__ uint32_t swz(uint32_t b) { return b ^ ((b >> 3) & 0x70); }

__device__ __forceinline__ void ldm_x4(uint32_t* r, uint32_t a) {
    asm volatile("ldmatrix.sync.aligned.m8n8.x4.shared.b16 {%0,%1,%2,%3}, [%4];"
        : "=r"(r[0]), "=r"(r[1]), "=r"(r[2]), "=r"(r[3]) : "r"(a));
}
__device__ __forceinline__ void mma_bf16(float* c, const uint32_t* a, const uint32_t* b) {
    asm volatile("mma.sync.aligned.m16n8k16.row.col.f32.bf16.bf16.f32 "
        "{%0,%1,%2,%3}, {%4,%5,%6,%7}, {%8,%9}, {%0,%1,%2,%3};"
        : "+f"(c[0]), "+f"(c[1]), "+f"(c[2]), "+f"(c[3])
        : "r"(a[0]), "r"(a[1]), "r"(a[2]), "r"(a[3]), "r"(b[0]), "r"(b[1]));
}
#define CP16(dst, src) \
    asm volatile("cp.async.cg.shared.global [%0], [%1], 16;" :: "r"(dst), "l"(src))
#define CP_COMMIT() asm volatile("cp.async.commit_group;" ::: "memory")
#define CP_WAITN(n) asm volatile("cp.async.wait_group %0;" :: "n"(n) : "memory")

__device__ __forceinline__ void split2(float f0, float f1, uint32_t& hi, uint32_t& lo) {
    __nv_bfloat16 h0 = __float2bfloat16(f0);
    __nv_bfloat16 h1 = __float2bfloat16(f1);
    __nv_bfloat16 l0 = __float2bfloat16(f0 - __bfloat162float(h0));
    __nv_bfloat16 l1 = __float2bfloat16(f1 - __bfloat162float(h1));
    hi = (uint32_t)__bfloat16_as_ushort(h0) | ((uint32_t)__bfloat16_as_ushort(h1) << 16);
    lo = (uint32_t)__bfloat16_as_ushort(l0) | ((uint32_t)__bfloat16_as_ushort(l1) << 16);
}

// ---------------- global scratch ----------------
__device__ __nv_bfloat16 g_WxT_hi[HH * DD];     // [n][k] = hi(Wx[k][n])
__device__ __nv_bfloat16 g_WxT_lo[HH * DD];
__device__ __nv_bfloat16 g_WhT_hi[HH * HH];     // [n][k] = hi(Wh[k][n])
__device__ __nv_bfloat16 g_WhT_lo[HH * HH];
__device__ __nv_bfloat16 g_h_hi[2][NB * HH];    // ping-pong split hidden state
__device__ __nv_bfloat16 g_h_lo[2][NB * HH];

// per-bm-group barrier state (padded: 32 unsigned = 128B apart)
__device__ unsigned g_genA[4 * 32];
__device__ unsigned g_cntA[4 * 32];

// ---------------- prep ----------------
__global__ void split_transpose_kernel(const float* __restrict__ W, int which) {
    __nv_bfloat16* hi = which ? g_WhT_hi : g_WxT_hi;
    __nv_bfloat16* lo = which ? g_WhT_lo : g_WxT_lo;
    __shared__ float tile[32][33];
    const int kb = blockIdx.x * 32, nb = blockIdx.y * 32;
    const int tx = threadIdx.x, ty = threadIdx.y;    // (32, 8)
#pragma unroll
    for (int i = 0; i < 4; ++i)
        tile[ty + 8 * i][tx] = W[(size_t)(kb + ty + 8 * i) * HH + nb + tx];
    __syncthreads();
#pragma unroll
    for (int i = 0; i < 4; ++i) {
        float f = tile[tx][ty + 8 * i];
        int n = nb + ty + 8 * i, k = kb + tx;
        __nv_bfloat16 h = __float2bfloat16(f);
        hi[(size_t)n * 1024 + k] = h;
        lo[(size_t)n * 1024 + k] = __float2bfloat16(f - __bfloat162float(h));
    }
}

__global__ void split_h0_kernel(const float* __restrict__ h0) {
    int i = blockIdx.x * blockDim.x + threadIdx.x;
    if (i < NB * HH) {
        float f = h0[i];
        __nv_bfloat16 h = __float2bfloat16(f);
        g_h_hi[1][i] = h;                            // step 0 reads parity 1
        g_h_lo[1][i] = __float2bfloat16(f - __bfloat162float(h));
    }
}

// =====================================================================
// Phase 1: out = x @ Wx + b.  CTA 128x128, 256 thr, 8 warps (2m x 4n),
// warp m64 x n32, k-chunks of 64. NEW: 2-stage B ring (cp.async
// pipelined across chunks). A staged synchronously (fp32->bf16 split).
// SMEM: AH 16K | AL 16K | B ring 2 x (hi 16K + lo 16K) = 96KB, occ 2.
// =====================================================================
#define P1_SMEM (98304 + 1024)

__global__ __launch_bounds__(256, 2)
void xw_gemm_kernel(const float* __restrict__ x, const float* __restrict__ bias,
                    float* __restrict__ out) {
    extern __shared__ char smem_raw[];
    char* smem = (char*)(((uintptr_t)smem_raw + 1023) & ~(uintptr_t)1023);
    const uint32_t sb = smem_u32(smem);
    const uint32_t AH = sb, AL = sb + 16384;
    const uint32_t Bbuf[2] = { sb + 32768, sb + 65536 };  // each: hi @0, lo @+16384

    const int tid = threadIdx.x, lane = tid & 31, w = tid >> 5;
    const int n1 = blockIdx.x * 128, m0 = blockIdx.y * 128;
    const int mq = w & 1, nq = w >> 1;

    const int li = lane >> 3, lr = lane & 7;
    const int aRow = mq * 64 + (li & 1) * 8 + lr;
    const int aKof = (li >> 1) * 16;
    const int bRow = nq * 32 + (li >> 1) * 8 + lr;
    const int bKof = (li & 1) * 16;

    const int sr = tid >> 3, su = tid & 7;

    float C[4][4][4];
#pragma unroll
    for (int i = 0; i < 4; ++i)
#pragma unroll
        for (int j = 0; j < 4; ++j)
#pragma unroll
            for (int q = 0; q < 4; ++q) C[i][j][q] = 0.0f;

    // prologue: B chunk 0 in flight
    {
        const uint32_t BB = Bbuf[0];
#pragma unroll
        for (int p = 0; p < 4; ++p) {
            const int row = p * 32 + sr;
            const uint32_t bo = swz((uint32_t)row * 128 + su * 16);
            CP16(BB + bo,         g_WxT_hi + (size_t)(n1 + row) * DD + su * 8);
            CP16(BB + 16384 + bo, g_WxT_lo + (size_t)(n1 + row) * DD + su * 8);
        }
        CP_COMMIT();
    }

    for (int c = 0; c < 16; ++c) {
        const int k0 = c * 64;
        // A: fp32 -> split bf16 (synchronous; overlaps with B(c) in flight)
#pragma unroll
        for (int p = 0; p < 4; ++p) {
            const int row = p * 32 + sr;
            const float* src = x + (size_t)(m0 + row) * DD + k0 + su * 8;
            float4 f0 = *(const float4*)src;
            float4 f1 = *(const float4*)(src + 4);
            uint32_t hw[4], lw[4];
            split2(f0.x, f0.y, hw[0], lw[0]);
            split2(f0.z, f0.w, hw[1], lw[1]);
            split2(f1.x, f1.y, hw[2], lw[2]);
            split2(f1.z, f1.w, hw[3], lw[3]);
            const uint32_t bo = swz((uint32_t)row * 128 + su * 16);
            *(uint4*)(smem + (AH - sb) + bo) = *(uint4*)hw;
            *(uint4*)(smem + (AL - sb) + bo) = *(uint4*)lw;
        }
        // issue B(c+1): target (c+1)&1 — safe: trailing sync of c-1 passed,
        // so no warp still reads buffer (c-1)&1 == (c+1)&1.
        if (c < 15) {
            const int k1 = (c + 1) * 64;
            const uint32_t BB = Bbuf[(c + 1) & 1];
#pragma unroll
            for (int p = 0; p < 4; ++p) {
                const int row = p * 32 + sr;
                const uint32_t bo = swz((uint32_t)row * 128 + su * 16);
                CP16(BB + bo,         g_WxT_hi + (size_t)(n1 + row) * DD + k1 + su * 8);
                CP16(BB + 16384 + bo, g_WxT_lo + (size_t)(n1 + row) * DD + k1 + su * 8);
            }
            CP_COMMIT();
            CP_WAITN(1);            // B(c) landed, B(c+1) in flight
        } else {
            CP_WAITN(0);
        }
        __syncthreads();

        const uint32_t BH = Bbuf[c & 1], BL = Bbuf[c & 1] + 16384;
#pragma unroll
        for (int kk = 0; kk < 64; kk += 16) {
            uint32_t Bh[2][4], Bl[2][4];
#pragma unroll
            for (int g = 0; g < 2; ++g) {
                const uint32_t bo = swz((uint32_t)(bRow + g * 16) * 128 + kk * 2 + bKof);
                ldm_x4(Bh[g], BH + bo);
                ldm_x4(Bl[g], BL + bo);
            }
#pragma unroll
            for (int mt = 0; mt < 4; ++mt) {
                uint32_t Ahf[4], Alf[4];
                const uint32_t ao = swz((uint32_t)(aRow + mt * 16) * 128 + kk * 2 + aKof);
                ldm_x4(Ahf, AH + ao);
                ldm_x4(Alf, AL + ao);
#pragma unroll
                for (int nt = 0; nt < 4; ++nt) {
                    const uint32_t* bh = &Bh[nt >> 1][(nt & 1) * 2];
                    const uint32_t* bl = &Bl[nt >> 1][(nt & 1) * 2];
                    mma_bf16(C[mt][nt], Ahf, bh);
                    mma_bf16(C[mt][nt], Ahf, bl);
                    mma_bf16(C[mt][nt], Alf, bh);
                }
            }
        }
        __syncthreads();            // protects A reuse + B ring parity
    }

#pragma unroll
    for (int mt = 0; mt < 4; ++mt) {
#pragma unroll
        for (int nt = 0; nt < 4; ++nt) {
            const int r  = m0 + mq * 64 + mt * 16 + (lane >> 2);
            const int cc = n1 + nq * 32 + nt * 8 + (lane & 3) * 2;
            const float b0 = bias[cc], b1 = bias[cc + 1];
            float2 v0 = { C[mt][nt][0] + b0, C[mt][nt][1] + b1 };
            float2 v1 = { C[mt][nt][2] + b0, C[mt][nt][3] + b1 };
            *(float2*)(out + (size_t)r * HH + cc)       = v0;
            *(float2*)(out + (size_t)(r + 8) * HH + cc) = v1;
        }
    }
}

// =====================================================================
// Phase 2: persistent scan (R9 structure, proven). 128 CTAs = 4
// independent bm-groups x 32 bn, tile 32x32, 128 thr (4 warps m16n16).
// Per-group 32-arrival ATOMIC barrier (proven). K-chunks of 128
// (8/step), 4-stage ring, 2-ahead issue, one sync per chunk.
// NEW (safe): 3 independent accumulators to shorten MMA dep chains.
// SMEM: A ring 4x16KB | BH 64K | BL 64K = 192KB.
// =====================================================================
#define GRID2 128
#define SC_SMEM (65536 + 131072 + 1024)

__device__ __forceinline__ void group_barrier(int g) {
    __syncthreads();
    if (threadIdx.x == 0) {
        __threadfence();
        volatile unsigned* genp = &g_genA[g * 32];
        unsigned my_gen = *genp;
        unsigned old = atomicAdd(&g_cntA[g * 32], 1u);
        if (old == 31) {
            atomicExch(&g_cntA[g * 32], 0u);
            __threadfence();
            atomicAdd((unsigned*)&g_genA[g * 32], 1u);
        } else {
            while (*genp == my_gen) { }
        }
        __threadfence();
    }
    __syncthreads();
}

// stage one 128-k chunk (2 sub-chunks of 64k) of the 32-row h M-slice
__device__ __forceinline__ void scan_issue_chunk(
        uint32_t stage,
        const __nv_bfloat16* __restrict__ rh, const __nv_bfloat16* __restrict__ rl,
        int m0, int c, int tid) {
    const int r2 = tid >> 3, u = tid & 7;
#pragma unroll
    for (int s = 0; s < 2; ++s) {
        const int k0 = (2 * c + s) * 64;
        const uint32_t base = stage + (uint32_t)s * 8192;
#pragma unroll
        for (int p = 0; p < 2; ++p) {
            const int row = p * 16 + r2;
            const uint32_t bo = swz((uint32_t)row * 128 + u * 16);
            CP16(base + bo,        rh + (size_t)(m0 + row) * HH + k0 + u * 8);
            CP16(base + 4096 + bo, rl + (size_t)(m0 + row) * HH + k0 + u * 8);
        }
    }
}

__global__ __launch_bounds__(128, 1)
void rnn_scan_kernel(float* __restrict__ out) {
    extern __shared__ char smem_raw[];
    char* smem = (char*)(((uintptr_t)smem_raw + 1023) & ~(uintptr_t)1023);
    const uint32_t sb = smem_u32(smem);
    const int tid = threadIdx.x, lane = tid & 31, w = tid >> 5;
    const int bm = blockIdx.x >> 5, bn = blockIdx.x & 31;
    const int m0 = bm * 32, n0 = bn * 32;

    const uint32_t BH = sb + 65536, BL = sb + 131072;  // 16 x 4KB (64k) blocks

    // stage resident B = WhT[n0..n0+31][:], 64k-block layout, swizzled
    {
        const int r2 = tid >> 3, u = tid & 7;
        for (int c = 0; c < 16; ++c) {
#pragma unroll
            for (int p = 0; p < 2; ++p) {
                const int row = p * 16 + r2;
                const uint32_t bo = (uint32_t)c * 4096 + swz((uint32_t)row * 128 + u * 16);
                *(uint4*)(smem + 65536 + bo) =
                    *(const uint4*)(g_WhT_hi + (size_t)(n0 + row) * HH + c * 64 + u * 8);
                *(uint4*)(smem + 131072 + bo) =
                    *(const uint4*)(g_WhT_lo + (size_t)(n0 + row) * HH + c * 64 + u * 8);
            }
        }
    }
    __syncthreads();

    const int mq = w & 1, nq = w >> 1;                // warp m16 x n16 tile
    const int li = lane >> 3, lr = lane & 7;
    const int aRow = mq * 16 + (li & 1) * 8 + lr;
    const int aKof = (li >> 1) * 16;
    const int bRow = nq * 16 + (li >> 1) * 8 + lr;
    const int bKof = (li & 1) * 16;

    const int r0 = m0 + mq * 16 + (lane >> 2);        // epilogue rows r0, r0+8
    const int cb = n0 + nq * 16 + (lane & 3) * 2;     // + nt*8

    for (int t = 0; t < TT; ++t) {
        const __nv_bfloat16* rh = g_h_hi[(t & 1) ^ 1];
        const __nv_bfloat16* rl = g_h_lo[(t & 1) ^ 1];
        __nv_bfloat16* wh = g_h_hi[t & 1];
        __nv_bfloat16* wl = g_h_lo[t & 1];

        // prologue: 2 chunks in flight
        scan_issue_chunk(sb,         rh, rl, m0, 0, tid); CP_COMMIT();
        scan_issue_chunk(sb + 16384, rh, rl, m0, 1, tid); CP_COMMIT();

        // prefetch xw slice for epilogue (overlaps with cp.async)
        float2 xp[2][2];
#pragma unroll
        for (int nt = 0; nt < 2; ++nt) {
            const float* p = out + ((size_t)r0 * TT + t) * HH + cb + nt * 8;
            xp[nt][0] = *(const float2*)p;
            xp[nt][1] = *(const float2*)(p + (size_t)8 * TT * HH);
        }

        float C1[2][4], C2[2][4], C3[2][4];           // 3 parallel chains
#pragma unroll
        for (int j = 0; j < 2; ++j)
#pragma unroll
            for (int q = 0; q < 4; ++q) { C1[j][q] = 0.f; C2[j][q] = 0.f; C3[j][q] = 0.f; }

        for (int c = 0; c < 8; ++c) {
            if (c + 2 < 8) {
                scan_issue_chunk(sb + (uint32_t)((c + 2) & 3) * 16384, rh, rl, m0, c + 2, tid);
                CP_COMMIT();
                CP_WAITN(2);         // chunk c landed; c+1, c+2 in flight
            } else if (c == 6) { CP_WAITN(1); }
            else               { CP_WAITN(0); }
            __syncthreads();         // single sync: ring(4) + 2-ahead => safe

            const uint32_t stage = sb + (uint32_t)(c & 3) * 16384;
#pragma unroll
            for (int s = 0; s < 2; ++s) {
                const uint32_t abase_h = stage + (uint32_t)s * 8192;
                const uint32_t abase_l = abase_h + 4096;
                const uint32_t bblk = (uint32_t)(2 * c + s) * 4096;
#pragma unroll
                for (int kk = 0; kk < 64; kk += 16) {
                    uint32_t Bhf[4], Blf[4];
                    const uint32_t bo = bblk + swz((uint32_t)bRow * 128 + kk * 2 + bKof);
                    ldm_x4(Bhf, BH + bo);
                    ldm_x4(Blf, BL + bo);
                    uint32_t Ahf[4], Alf[4];
                    const uint32_t ao = swz((uint32_t)aRow * 128 + kk * 2 + aKof);
                    ldm_x4(Ahf, abase_h + ao);
                    ldm_x4(Alf, abase_l + ao);
#pragma unroll
                    for (int nt = 0; nt < 2; ++nt) {
                        mma_bf16(C1[nt], Ahf, &Bhf[nt * 2]);
                        mma_bf16(C2[nt], Ahf, &Blf[nt * 2]);
                        mma_bf16(C3[nt], Alf, &Bhf[nt * 2]);
                    }
                }
            }
        }

        // epilogue: h = tanh(xw + C1+C2+C3)
#pragma unroll
        for (int nt = 0; nt < 2; ++nt) {
            const int cc = cb + nt * 8;
            float a0 = C1[nt][0] + C2[nt][0] + C3[nt][0];
            float a1 = C1[nt][1] + C2[nt][1] + C3[nt][1];
            float a2 = C1[nt][2] + C2[nt][2] + C3[nt][2];
            float a3 = C1[nt][3] + C2[nt][3] + C3[nt][3];
            float h00 = tanhf(xp[nt][0].x + a0);
            float h01 = tanhf(xp[nt][0].y + a1);
            float h10 = tanhf(xp[nt][1].x + a2);
            float h11 = tanhf(xp[nt][1].y + a3);
            float* p = out + ((size_t)r0 * TT + t) * HH + cc;
            float2 v0 = { h00, h01 }, v1 = { h10, h11 };
            *(float2*)p = v0;
            *(float2*)(p + (size_t)8 * TT * HH) = v1;
            uint32_t hi, lo;
            split2(h00, h01, hi, lo);
            *(uint32_t*)(wh + (size_t)r0 * HH + cc) = hi;
            *(uint32_t*)(wl + (size_t)r0 * HH + cc) = lo;
            split2(h10, h11, hi, lo);
            *(uint32_t*)(wh + (size_t)(r0 + 8) * HH + cc) = hi;
            *(uint32_t*)(wl + (size_t)(r0 + 8) * HH + cc) = lo;
        }

        group_barrier(bm);   // only the 32 CTAs sharing this bm must sync
    }
}

// ---------------- launch ----------------
extern "C" void kernel_launch(void* const* d_in, const int* in_sizes, int n_in,
                              void* d_out, int out_size)
{
    const float* x  = (const float*)d_in[0];
    const float* h0 = (const float*)d_in[1];
    const float* Wx = (const float*)d_in[2];
    const float* Wh = (const float*)d_in[3];
    const float* b  = (const float*)d_in[4];
    float* out = (float*)d_out;

    cudaFuncSetAttribute(xw_gemm_kernel,
        cudaFuncAttributeMaxDynamicSharedMemorySize, P1_SMEM);
    cudaFuncSetAttribute(rnn_scan_kernel,
        cudaFuncAttributeMaxDynamicSharedMemorySize, SC_SMEM);

    dim3 tb(32, 8);
    split_transpose_kernel<<<dim3(32, 32), tb>>>(Wx, 0);
    split_transpose_kernel<<<dim3(32, 32), tb>>>(Wh, 1);
    split_h0_kernel<<<(NB * HH + 255) / 256, 256>>>(h0);

    xw_gemm_kernel<<<dim3(8, 512), 256, P1_SMEM>>>(x, b, out);
    rnn_scan_kernel<<<GRID2, 128, SC_SMEM>>>(out);
}

// round 14
// speedup vs baseline: 1.1301x; 1.1301x over previous
#include <cuda_runtime.h>
#include <cuda_bf16.h>
#include <math.h>
#include <stdint.h>

#define NB 128
#define TT 512
#define DD 1024
#define HH 1024

// ---------------- helpers (arch-agnostic PTX only: sm_80+ features) ----------
__device__ __forceinline__ uint32_t smem_u32(const void* p) {
    uint32_t a;
    asm("{ .reg .u64 t; cvta.to.shared.u64 t, %1; cvt.u32.u64 %0, t; }"
        : "=r"(a) : "l"(p));
    return a;
}
__device__ __forceinline__ uint32_t swz(uint32_t b) { return b ^ ((b >> 3) & 0x70); }

__device__ __forceinline__ void ldm_x4(uint32_t* r, uint32_t a) {
    asm volatile("ldmatrix.sync.aligned.m8n8.x4.shared.b16 {%0,%1,%2,%3}, [%4];"
        : "=r"(r[0]), "=r"(r[1]), "=r"(r[2]), "=r"(r[3]) : "r"(a));
}
__device__ __forceinline__ void mma_bf16(float* c, const uint32_t* a, const uint32_t* b) {
    asm volatile("mma.sync.aligned.m16n8k16.row.col.f32.bf16.bf16.f32 "
        "{%0,%1,%2,%3}, {%4,%5,%6,%7}, {%8,%9}, {%0,%1,%2,%3};"
        : "+f"(c[0]), "+f"(c[1]), "+f"(c[2]), "+f"(c[3])
        : "r"(a[0]), "r"(a[1]), "r"(a[2]), "r"(a[3]), "r"(b[0]), "r"(b[1]));
}
#define CP16(dst, src) \
    asm volatile("cp.async.cg.shared.global [%0], [%1], 16;" :: "r"(dst), "l"(src))
#define CP_COMMIT() asm volatile("cp.async.commit_group;" ::: "memory")
#define CP_WAITN(n) asm volatile("cp.async.wait_group %0;" :: "n"(n) : "memory")

__device__ __forceinline__ void split2(float f0, float f1, uint32_t& hi, uint32_t& lo) {
    __nv_bfloat16 h0 = __float2bfloat16(f0);
    __nv_bfloat16 h1 = __float2bfloat16(f1);
    __nv_bfloat16 l0 = __float2bfloat16(f0 - __bfloat162float(h0));
    __nv_bfloat16 l1 = __float2bfloat16(f1 - __bfloat162float(h1));
    hi = (uint32_t)__bfloat16_as_ushort(h0) | ((uint32_t)__bfloat16_as_ushort(h1) << 16);
    lo = (uint32_t)__bfloat16_as_ushort(l0) | ((uint32_t)__bfloat16_as_ushort(l1) << 16);
}

// ---------------- global scratch ----------------
__device__ __nv_bfloat16 g_WxT_hi[HH * DD];     // [n][k] = hi(Wx[k][n])
__device__ __nv_bfloat16 g_WxT_lo[HH * DD];
__device__ __nv_bfloat16 g_WhT_hi[HH * HH];     // [n][k] = hi(Wh[k][n])
__device__ __nv_bfloat16 g_WhT_lo[HH * HH];
__device__ __nv_bfloat16 g_h_hi[2][NB * HH];    // ping-pong split hidden state
__device__ __nv_bfloat16 g_h_lo[2][NB * HH];

// per-bm-group barrier state (padded: 32 unsigned = 128B apart)
__device__ unsigned g_genA[4 * 32];
__device__ unsigned g_cntA[4 * 32];

// ---------------- prep ----------------
__global__ void split_transpose_kernel(const float* __restrict__ W, int which) {
    __nv_bfloat16* hi = which ? g_WhT_hi : g_WxT_hi;
    __nv_bfloat16* lo = which ? g_WhT_lo : g_WxT_lo;
    __shared__ float tile[32][33];
    const int kb = blockIdx.x * 32, nb = blockIdx.y * 32;
    const int tx = threadIdx.x, ty = threadIdx.y;    // (32, 8)
#pragma unroll
    for (int i = 0; i < 4; ++i)
        tile[ty + 8 * i][tx] = W[(size_t)(kb + ty + 8 * i) * HH + nb + tx];
    __syncthreads();
#pragma unroll
    for (int i = 0; i < 4; ++i) {
        float f = tile[tx][ty + 8 * i];
        int n = nb + ty + 8 * i, k = kb + tx;
        __nv_bfloat16 h = __float2bfloat16(f);
        hi[(size_t)n * 1024 + k] = h;
        lo[(size_t)n * 1024 + k] = __float2bfloat16(f - __bfloat162float(h));
    }
}

__global__ void split_h0_kernel(const float* __restrict__ h0) {
    int i = blockIdx.x * blockDim.x + threadIdx.x;
    if (i < NB * HH) {
        float f = h0[i];
        __nv_bfloat16 h = __float2bfloat16(f);
        g_h_hi[1][i] = h;                            // step 0 reads parity 1
        g_h_lo[1][i] = __float2bfloat16(f - __bfloat162float(h));
    }
}

// =====================================================================
// Phase 1: out = x @ Wx + b.  (R7/R9 exact version — proven 65% tensor)
// =====================================================================
#define P1_SMEM (65536 + 1024)

__global__ __launch_bounds__(256, 2)
void xw_gemm_kernel(const float* __restrict__ x, const float* __restrict__ bias,
                    float* __restrict__ out) {
    extern __shared__ char smem_raw[];
    char* smem = (char*)(((uintptr_t)smem_raw + 1023) & ~(uintptr_t)1023);
    const uint32_t sb = smem_u32(smem);
    const uint32_t AH = sb, AL = sb + 16384, BH = sb + 32768, BL = sb + 49152;

    const int tid = threadIdx.x, lane = tid & 31, w = tid >> 5;
    const int n1 = blockIdx.x * 128, m0 = blockIdx.y * 128;
    const int mq = w & 1, nq = w >> 1;

    const int li = lane >> 3, lr = lane & 7;
    const int aRow = mq * 64 + (li & 1) * 8 + lr;
    const int aKof = (li >> 1) * 16;
    const int bRow = nq * 32 + (li >> 1) * 8 + lr;
    const int bKof = (li & 1) * 16;

    const int sr = tid >> 3, su = tid & 7;

    float C[4][4][4];
#pragma unroll
    for (int i = 0; i < 4; ++i)
#pragma unroll
        for (int j = 0; j < 4; ++j)
#pragma unroll
            for (int q = 0; q < 4; ++q) C[i][j][q] = 0.0f;

    for (int c = 0; c < 16; ++c) {
        const int k0 = c * 64;
#pragma unroll
        for (int p = 0; p < 4; ++p) {
            const int row = p * 32 + sr;
            const uint32_t bo = swz((uint32_t)row * 128 + su * 16);
            CP16(BH + bo, g_WxT_hi + (size_t)(n1 + row) * DD + k0 + su * 8);
            CP16(BL + bo, g_WxT_lo + (size_t)(n1 + row) * DD + k0 + su * 8);
        }
        CP_COMMIT();
#pragma unroll
        for (int p = 0; p < 4; ++p) {
            const int row = p * 32 + sr;
            const float* src = x + (size_t)(m0 + row) * DD + k0 + su * 8;
            float4 f0 = *(const float4*)src;
            float4 f1 = *(const float4*)(src + 4);
            uint32_t hw[4], lw[4];
            split2(f0.x, f0.y, hw[0], lw[0]);
            split2(f0.z, f0.w, hw[1], lw[1]);
            split2(f1.x, f1.y, hw[2], lw[2]);
            split2(f1.z, f1.w, hw[3], lw[3]);
            const uint32_t bo = swz((uint32_t)row * 128 + su * 16);
            *(uint4*)(smem + (AH - sb) + bo) = *(uint4*)hw;
            *(uint4*)(smem + (AL - sb) + bo) = *(uint4*)lw;
        }
        CP_WAITN(0);
        __syncthreads();

#pragma unroll
        for (int kk = 0; kk < 64; kk += 16) {
            uint32_t Bh[2][4], Bl[2][4];
#pragma unroll
            for (int g = 0; g < 2; ++g) {
                const uint32_t bo = swz((uint32_t)(bRow + g * 16) * 128 + kk * 2 + bKof);
                ldm_x4(Bh[g], BH + bo);
                ldm_x4(Bl[g], BL + bo);
            }
#pragma unroll
            for (int mt = 0; mt < 4; ++mt) {
                uint32_t Ahf[4], Alf[4];
                const uint32_t ao = swz((uint32_t)(aRow + mt * 16) * 128 + kk * 2 + aKof);
                ldm_x4(Ahf, AH + ao);
                ldm_x4(Alf, AL + ao);
#pragma unroll
                for (int nt = 0; nt < 4; ++nt) {
                    const uint32_t* bh = &Bh[nt >> 1][(nt & 1) * 2];
                    const uint32_t* bl = &Bl[nt >> 1][(nt & 1) * 2];
                    mma_bf16(C[mt][nt], Ahf, bh);
                    mma_bf16(C[mt][nt], Ahf, bl);
                    mma_bf16(C[mt][nt], Alf, bh);
                }
            }
        }
        __syncthreads();
    }

#pragma unroll
    for (int mt = 0; mt < 4; ++mt) {
#pragma unroll
        for (int nt = 0; nt < 4; ++nt) {
            const int r  = m0 + mq * 64 + mt * 16 + (lane >> 2);
            const int cc = n1 + nq * 32 + nt * 8 + (lane & 3) * 2;
            const float b0 = bias[cc], b1 = bias[cc + 1];
            float2 v0 = { C[mt][nt][0] + b0, C[mt][nt][1] + b1 };
            float2 v1 = { C[mt][nt][2] + b0, C[mt][nt][3] + b1 };
            *(float2*)(out + (size_t)r * HH + cc)       = v0;
            *(float2*)(out + (size_t)(r + 8) * HH + cc) = v1;
        }
    }
}

// =====================================================================
// Phase 2: persistent scan (R9 skeleton, proven). 128 CTAs = 4 bm-
// groups x 32 bn, tile 32x32. NEW: 256 thr, 8 warps, TWO warpgroups
// k-split: wg0 (warps 0-3, R9's exact m16n16 map) handles sub-chunk
// s=0, wg1 handles s=1. Partials merged via SMEM once per step; wg0
// runs R9's unchanged epilogue. Atomic group barrier verbatim.
// SMEM: A ring 4x16KB | BH 64K | BL 64K = 192KB.
// =====================================================================
#define GRID2 128
#define SC_SMEM (65536 + 131072 + 1024)

__device__ __forceinline__ void group_barrier(int g) {
    __syncthreads();
    if (threadIdx.x == 0) {
        __threadfence();
        volatile unsigned* genp = &g_genA[g * 32];
        unsigned my_gen = *genp;
        unsigned old = atomicAdd(&g_cntA[g * 32], 1u);
        if (old == 31) {
            atomicExch(&g_cntA[g * 32], 0u);
            __threadfence();
            atomicAdd((unsigned*)&g_genA[g * 32], 1u);
        } else {
            while (*genp == my_gen) { }
        }
        __threadfence();
    }
    __syncthreads();
}

// stage one 128-k chunk (both 64k sub-chunks), 256 thr: 4 CP16 each
__device__ __forceinline__ void scan_issue_chunk(
        uint32_t stage,
        const __nv_bfloat16* __restrict__ rh, const __nv_bfloat16* __restrict__ rl,
        int m0, int c, int tid) {
    const int rr = tid >> 3, uu = tid & 7;           // row 0..31, 16B seg 0..7
    const uint32_t bo = swz((uint32_t)rr * 128 + uu * 16);
#pragma unroll
    for (int s = 0; s < 2; ++s) {
        const int k0 = (2 * c + s) * 64;
        const uint32_t base = stage + (uint32_t)s * 8192;
        CP16(base + bo,        rh + (size_t)(m0 + rr) * HH + k0 + uu * 8);
        CP16(base + 4096 + bo, rl + (size_t)(m0 + rr) * HH + k0 + uu * 8);
    }
}

__global__ __launch_bounds__(256, 1)
void rnn_scan_kernel(float* __restrict__ out) {
    extern __shared__ char smem_raw[];
    char* smem = (char*)(((uintptr_t)smem_raw + 1023) & ~(uintptr_t)1023);
    const uint32_t sb = smem_u32(smem);
    const int tid = threadIdx.x, lane = tid & 31, w = tid >> 5;
    const int wg = w >> 2, wl = w & 3;               // warpgroup, warp-in-group
    const int bm = blockIdx.x >> 5, bn = blockIdx.x & 31;
    const int m0 = bm * 32, n0 = bn * 32;

    const uint32_t BH = sb + 65536, BL = sb + 131072; // 16 x 4KB (64k) blocks

    // stage resident B = WhT[n0..n0+31][:], 64k-block layout, swizzled (256 thr)
    {
        const int rr = tid >> 3, uu = tid & 7;
        const uint32_t bo0 = swz((uint32_t)rr * 128 + uu * 16);
        for (int c = 0; c < 16; ++c) {
            *(uint4*)(smem + 65536 + c * 4096 + bo0) =
                *(const uint4*)(g_WhT_hi + (size_t)(n0 + rr) * HH + c * 64 + uu * 8);
            *(uint4*)(smem + 131072 + c * 4096 + bo0) =
                *(const uint4*)(g_WhT_lo + (size_t)(n0 + rr) * HH + c * 64 + uu * 8);
        }
    }
    __syncthreads();

    // R9's exact 4-warp m16n16 map, indexed by warp-in-group
    const int mq = wl & 1, nq = wl >> 1;
    const int li = lane >> 3, lr = lane & 7;
    const int aRow = mq * 16 + (li & 1) * 8 + lr;
    const int aKof = (li >> 1) * 16;
    const int bRow = nq * 16 + (li >> 1) * 8 + lr;
    const int bKof = (li & 1) * 16;

    const int r0 = m0 + mq * 16 + (lane >> 2);        // epilogue rows r0, r0+8
    const int cb = n0 + nq * 16 + (lane & 3) * 2;     // + nt*8

    for (int t = 0; t < TT; ++t) {
        const __nv_bfloat16* rh = g_h_hi[(t & 1) ^ 1];
        const __nv_bfloat16* rl = g_h_lo[(t & 1) ^ 1];
        __nv_bfloat16* whp = g_h_hi[t & 1];
        __nv_bfloat16* wlp = g_h_lo[t & 1];

        // prologue: 2 chunks in flight (R9 shape)
        scan_issue_chunk(sb,         rh, rl, m0, 0, tid); CP_COMMIT();
        scan_issue_chunk(sb + 16384, rh, rl, m0, 1, tid); CP_COMMIT();

        // prefetch xw slice for epilogue (wg0 only — it owns the epilogue)
        float2 xp[2][2];
        if (wg == 0) {
#pragma unroll
            for (int nt = 0; nt < 2; ++nt) {
                const float* p = out + ((size_t)r0 * TT + t) * HH + cb + nt * 8;
                xp[nt][0] = *(const float2*)p;
                xp[nt][1] = *(const float2*)(p + (size_t)8 * TT * HH);
            }
        }

        float C[2][4];                                // this wg's k-partial
#pragma unroll
        for (int j = 0; j < 2; ++j)
#pragma unroll
            for (int q = 0; q < 4; ++q) C[j][q] = 0.0f;

        for (int c = 0; c < 8; ++c) {
            if (c + 2 < 8) {
                scan_issue_chunk(sb + (uint32_t)((c + 2) & 3) * 16384, rh, rl, m0, c + 2, tid);
                CP_COMMIT();
                CP_WAITN(2);         // chunk c landed; c+1, c+2 in flight
            } else if (c == 6) { CP_WAITN(1); }
            else               { CP_WAITN(0); }
            __syncthreads();         // single sync: ring(4) + 2-ahead => safe

            const uint32_t stage = sb + (uint32_t)(c & 3) * 16384;
            // this warpgroup's sub-chunk only (k-split)
            const uint32_t abase_h = stage + (uint32_t)wg * 8192;
            const uint32_t abase_l = abase_h + 4096;
            const uint32_t bblk = (uint32_t)(2 * c + wg) * 4096;
#pragma unroll
            for (int kk = 0; kk < 64; kk += 16) {
                uint32_t Bhf[4], Blf[4];
                const uint32_t bo = bblk + swz((uint32_t)bRow * 128 + kk * 2 + bKof);
                ldm_x4(Bhf, BH + bo);
                ldm_x4(Blf, BL + bo);
                uint32_t Ahf[4], Alf[4];
                const uint32_t ao = swz((uint32_t)aRow * 128 + kk * 2 + aKof);
                ldm_x4(Ahf, abase_h + ao);
                ldm_x4(Alf, abase_l + ao);
#pragma unroll
                for (int nt = 0; nt < 2; ++nt) {
                    mma_bf16(C[nt], Ahf, &Bhf[nt * 2]);
                    mma_bf16(C[nt], Ahf, &Blf[nt * 2]);
                    mma_bf16(C[nt], Alf, &Bhf[nt * 2]);
                }
            }
        }

        // merge wg1's partial into wg0 via SMEM scratch (stage 0 is dead now)
        __syncthreads();
        if (wg == 1) {
            float* scr = (float*)(smem + (size_t)(tid - 128) * 32);
#pragma unroll
            for (int j = 0; j < 2; ++j)
#pragma unroll
                for (int q = 0; q < 4; ++q) scr[j * 4 + q] = C[j][q];
        }
        __syncthreads();

        if (wg == 0) {
            const float* scr = (const float*)(smem + (size_t)tid * 32);
            // epilogue: h = tanh(xw + C_wg0 + C_wg1)   (R9 epilogue unchanged)
#pragma unroll
            for (int nt = 0; nt < 2; ++nt) {
                const int cc = cb + nt * 8;
                float a0 = C[nt][0] + scr[nt * 4 + 0];
                float a1 = C[nt][1] + scr[nt * 4 + 1];
                float a2 = C[nt][2] + scr[nt * 4 + 2];
                float a3 = C[nt][3] + scr[nt * 4 + 3];
                float h00 = tanhf(xp[nt][0].x + a0);
                float h01 = tanhf(xp[nt][0].y + a1);
                float h10 = tanhf(xp[nt][1].x + a2);
                float h11 = tanhf(xp[nt][1].y + a3);
                float* p = out + ((size_t)r0 * TT + t) * HH + cc;
                float2 v0 = { h00, h01 }, v1 = { h10, h11 };
                *(float2*)p = v0;
                *(float2*)(p + (size_t)8 * TT * HH) = v1;
                uint32_t hi, lo;
                split2(h00, h01, hi, lo);
                *(uint32_t*)(whp + (size_t)r0 * HH + cc) = hi;
                *(uint32_t*)(wlp + (size_t)r0 * HH + cc) = lo;
                split2(h10, h11, hi, lo);
                *(uint32_t*)(whp + (size_t)(r0 + 8) * HH + cc) = hi;
                *(uint32_t*)(wlp + (size_t)(r0 + 8) * HH + cc) = lo;
            }
        }

        group_barrier(bm);   // only the 32 CTAs sharing this bm must sync
    }
}

// ---------------- launch ----------------
extern "C" void kernel_launch(void* const* d_in, const int* in_sizes, int n_in,
                              void* d_out, int out_size)
{
    const float* x  = (const float*)d_in[0];
    const float* h0 = (const float*)d_in[1];
    const float* Wx = (const float*)d_in[2];
    const float* Wh = (const float*)d_in[3];
    const float* b  = (const float*)d_in[4];
    float* out = (float*)d_out;

    cudaFuncSetAttribute(xw_gemm_kernel,
        cudaFuncAttributeMaxDynamicSharedMemorySize, P1_SMEM);
    cudaFuncSetAttribute(rnn_scan_kernel,
        cudaFuncAttributeMaxDynamicSharedMemorySize, SC_SMEM);

    dim3 tb(32, 8);
    split_transpose_kernel<<<dim3(32, 32), tb>>>(Wx, 0);
    split_transpose_kernel<<<dim3(32, 32), tb>>>(Wh, 1);
    split_h0_kernel<<<(NB * HH + 255) / 256, 256>>>(h0);

    xw_gemm_kernel<<<dim3(8, 512), 256, P1_SMEM>>>(x, b, out);
    rnn_scan_kernel<<<GRID2, 256, SC_SMEM>>>(out);
}